// round 17
// baseline (speedup 1.0000x reference)
#include <cuda_runtime.h>
#include <cuda.h>
#include <cstdint>

// Bilinear flow warp: TMA-filled fp32 SMEM strips with HW 128B swizzle to
// decorrelate row banks (tile layout [xchunk][row][32 floats]); 2 channels
// per buffer, double-buffered, 256 threads x 2 blocks/SM.
//   img: [B=8, C=16, H=512, W=512] f32
//   flo: [B=8, 2,   H=512, W=512] f32
//   out: [B=8, C=16, H=512, W=512] f32

#define B_    8
#define C_    16
#define H_    512
#define W_    512
#define HW_   (H_ * W_)
#define TY    4
#define HALO  4
#define TROWS (TY + 2 * HALO)             // 12
#define THREADS 256
#define NCOL  2
#define NPIX  (TY * NCOL)                  // 8 pixels per thread
#define CH_FLOATS (16 * TROWS * 32)        // 6144 per channel (16 chunks)
#define PAIR_FLOATS (2 * CH_FLOATS)        // 12288
#define PAIR_BYTES  (PAIR_FLOATS * 4)      // 49152
#define SMEM_BYTES  (2 * PAIR_BYTES + 1024 + 64)
#define FB_BIT (1 << 22)
#define NPAIRS (C_ / 2)                    // 8

__device__ __forceinline__ void mbar_init(uint32_t a, uint32_t cnt) {
    asm volatile("mbarrier.init.shared.b64 [%0], %1;" :: "r"(a), "r"(cnt) : "memory");
}
__device__ __forceinline__ void mbar_expect(uint32_t a, uint32_t bytes) {
    asm volatile("mbarrier.arrive.expect_tx.shared.b64 _, [%0], %1;"
                 :: "r"(a), "r"(bytes) : "memory");
}
__device__ __forceinline__ void mbar_wait(uint32_t a, int ph) {
    asm volatile(
        "{\n\t.reg .pred P;\n"
        "W%=:\n\t"
        "mbarrier.try_wait.parity.acquire.cta.shared::cta.b64 P, [%0], %1, 0x989680;\n\t"
        "@P bra D%=;\n\t"
        "bra W%=;\n"
        "D%=:\n\t}"
        :: "r"(a), "r"(ph) : "memory");
}
__device__ __forceinline__ void tma4d(uint32_t dst, const CUtensorMap* m,
                                      int c0, int c1, int c2, int c3, uint32_t mbar) {
    asm volatile(
        "cp.async.bulk.tensor.4d.shared::cta.global.tile.mbarrier::complete_tx::bytes "
        "[%0], [%1, {%2, %3, %4, %5}], [%6];"
        :: "r"(dst), "l"(m), "r"(c0), "r"(c1), "r"(c2), "r"(c3), "r"(mbar) : "memory");
}

__global__ __launch_bounds__(THREADS, 2) void warp_bilinear_tma_kernel(
    const __grid_constant__ CUtensorMap tmap,
    const float* __restrict__ img,
    const float* __restrict__ flo,
    float* __restrict__ out)
{
    extern __shared__ float smem_raw[];
    // Force tile region to ABSOLUTE 1024B alignment so the HW swizzle key
    // (= addr bits [9:7]) matches our computed key.
    uint32_t su = (uint32_t)__cvta_generic_to_shared(smem_raw);
    const uint32_t pad = (1024u - (su & 1023u)) & 1023u;
    const uint32_t tiles_u32 = su + pad;
    float* tiles = smem_raw + (pad >> 2);
    const uint32_t mb = tiles_u32 + 2 * PAIR_BYTES;   // two 8B mbarriers

    const int bx = blockIdx.x;             // 0..1023
    const int b  = bx >> 7;                // 128 strips per batch
    const int h0 = (bx & 127) * TY;
    const int w0 = threadIdx.x;            // first column; second is w0+256
    const int row_lo = h0 - HALO;
    const int plane0 = b * C_;

    if (threadIdx.x == 0) {
        mbar_init(mb, 1);
        mbar_init(mb + 8, 1);
        asm volatile("fence.proxy.async.shared::cta;" ::: "memory");
    }
    __syncthreads();

    if (threadIdx.x == 0) {                // fill channels {0,1}
        mbar_expect(mb, PAIR_BYTES);
        tma4d(tiles_u32, &tmap, 0, row_lo, 0, plane0, mb);
    }

    // ---- Per-pixel geometry: 4 rows x 2 columns per thread ----
    // pk (fb=0): x0 | f2<<10 | dx<<20 | dy<<21
    // pk (fb=1): x0 | y0<<10 | dx<<20 | dy<<21 | FB_BIT
    float xw[NPIX], yw[NPIX];
    int   pk[NPIX];

    const int flo_b = (b * 2) * HW_;
    #pragma unroll
    for (int i = 0; i < TY; i++) {
        #pragma unroll
        for (int j = 0; j < NCOL; j++) {
            int q = i * NCOL + j;
            int h = h0 + i;
            int x = w0 + j * 256;
            float fx = __ldg(flo + flo_b + h * W_ + x);
            float fy = __ldg(flo + flo_b + HW_ + h * W_ + x);

            float px = (float)x + fx;
            float py = (float)h + fy;
            float x0f = floorf(px);
            float y0f = floorf(py);
            xw[q] = px - x0f;              // weights from UNclamped floor
            yw[q] = py - y0f;

            int x0 = (int)fminf(fmaxf(x0f,        0.0f), (float)(W_ - 1));
            int x1 = (int)fminf(fmaxf(x0f + 1.0f, 0.0f), (float)(W_ - 1));
            int y0 = (int)fminf(fmaxf(y0f,        0.0f), (float)(H_ - 1));
            int y1 = (int)fminf(fmaxf(y0f + 1.0f, 0.0f), (float)(H_ - 1));

            int dx = x1 - x0;
            int dy = y1 - y0;
            int fb = (y0 < row_lo) || (y1 > row_lo + TROWS - 1);
            pk[q] = fb ? (x0 | (y0 << 10) | (dx << 20) | (dy << 21) | FB_BIT)
                       : (x0 | ((y0 - row_lo) << 10) | (dx << 20) | (dy << 21));
        }
    }

    const float* bimg = img + (size_t)b * C_ * HW_;
    int ph0 = 0, ph1 = 0;

    for (int t = 0; t < NPAIRS; t++) {     // 8 channel pairs
        const int s = t & 1;
        if (threadIdx.x == 0 && t + 1 < NPAIRS) {
            uint32_t mbn = mb + 8 * (1 - s);
            mbar_expect(mbn, PAIR_BYTES);
            tma4d(tiles_u32 + (1 - s) * PAIR_BYTES, &tmap,
                  0, row_lo, 0, plane0 + 2 * (t + 1), mbn);
        }
        if (s == 0) { mbar_wait(mb, ph0);     ph0 ^= 1; }
        else        { mbar_wait(mb + 8, ph1); ph1 ^= 1; }

        const float* tA = tiles + s * PAIR_FLOATS;         // channel 2t
        const float* tB = tA + CH_FLOATS;                  // channel 2t+1
        const float* pA = bimg + (size_t)(2 * t)     * HW_;
        const float* pB = bimg + (size_t)(2 * t + 1) * HW_;
        float* oA = out + ((size_t)(b * C_ + 2 * t))     * HW_;
        float* oB = out + ((size_t)(b * C_ + 2 * t + 1)) * HW_;

        #pragma unroll
        for (int i = 0; i < TY; i++) {
            #pragma unroll
            for (int j = 0; j < NCOL; j++) {
                int q = i * NCOL + j;
                int p = pk[q];

                float Ia0, Ib0, Ic0, Id0, Ia1, Ib1, Ic1, Id1;
                if (!(p & FB_BIT)) {
                    int x0 = p & 1023;
                    int f2 = (p >> 10) & 15;
                    int dx = (p >> 20) & 1;
                    int dy = (p >> 21) & 1;
                    int x1 = x0 + dx;
                    int r1 = f2 + dy;
                    int xc0 = x0 >> 5, xi0 = x0 & 31;
                    int xc1 = x1 >> 5, xi1 = x1 & 31;
                    // tile layout: [xc][r][32], swizzle key = (xc*12+r)&7 =
                    // (xc*4+r)&7, applied as xi ^ (key<<2)
                    int oa = xc0 * 384 + f2 * 32 + (xi0 ^ ((((xc0 << 2) + f2) & 7) << 2));
                    int ob = xc0 * 384 + r1 * 32 + (xi0 ^ ((((xc0 << 2) + r1) & 7) << 2));
                    int oc = xc1 * 384 + f2 * 32 + (xi1 ^ ((((xc1 << 2) + f2) & 7) << 2));
                    int od = xc1 * 384 + r1 * 32 + (xi1 ^ ((((xc1 << 2) + r1) & 7) << 2));
                    Ia0 = tA[oa];  Ib0 = tA[ob];  Ic0 = tA[oc];  Id0 = tA[od];
                    Ia1 = tB[oa];  Ib1 = tB[ob];  Ic1 = tB[oc];  Id1 = tB[od];
                } else {
                    int x0 = p & 1023;
                    int y0 = (p >> 10) & 1023;
                    int dx = (p >> 20) & 1;
                    int dy = (p >> 21) & 1;
                    int g  = y0 * W_ + x0;
                    int g1 = g + dy * W_;
                    Ia0 = __ldg(pA + g);  Ic0 = __ldg(pA + g + dx);
                    Ib0 = __ldg(pA + g1); Id0 = __ldg(pA + g1 + dx);
                    Ia1 = __ldg(pB + g);  Ic1 = __ldg(pB + g + dx);
                    Ib1 = __ldg(pB + g1); Id1 = __ldg(pB + g1 + dx);
                }

                float xwv = xw[q], ywv = yw[q];
                float wa = (1.0f - xwv) * (1.0f - ywv);
                float wb = (1.0f - xwv) * ywv;
                float wc = xwv * (1.0f - ywv);
                float wd = xwv * ywv;

                float r0 = wa * Ia0;
                float r1v = wa * Ia1;
                r0 = fmaf(wb, Ib0, r0);   r1v = fmaf(wb, Ib1, r1v);
                r0 = fmaf(wc, Ic0, r0);   r1v = fmaf(wc, Ic1, r1v);
                r0 = fmaf(wd, Id0, r0);   r1v = fmaf(wd, Id1, r1v);

                int off = (h0 + i) * W_ + w0 + j * 256;
                oA[off] = r0;
                oB[off] = r1v;
            }
        }

        __syncthreads();                   // buffer s fully read before refill
    }
}

// ---- Fallback: proven direct-gather kernel (R1) ----
__global__ __launch_bounds__(256) void warp_bilinear_direct_kernel(
    const float* __restrict__ img,
    const float* __restrict__ flo,
    float* __restrict__ out)
{
    int idx = blockIdx.x * blockDim.x + threadIdx.x;
    if (idx >= B_ * HW_) return;
    int w = idx & (W_ - 1);
    int t = idx >> 9;
    int h = t & (H_ - 1);
    int b = t >> 9;

    int flo_base = ((b * 2) * H_ + h) * W_ + w;
    float fx = __ldg(flo + flo_base);
    float fy = __ldg(flo + flo_base + HW_);
    float px = (float)w + fx;
    float py = (float)h + fy;
    float x0f = floorf(px), y0f = floorf(py);
    float xw = px - x0f, yw = py - y0f;
    int x0 = (int)fminf(fmaxf(x0f,        0.0f), (float)(W_ - 1));
    int x1 = (int)fminf(fmaxf(x0f + 1.0f, 0.0f), (float)(W_ - 1));
    int y0 = (int)fminf(fmaxf(y0f,        0.0f), (float)(H_ - 1));
    int y1 = (int)fminf(fmaxf(y0f + 1.0f, 0.0f), (float)(H_ - 1));
    float wa = (1.0f - xw) * (1.0f - yw);
    float wb = (1.0f - xw) * yw;
    float wc = xw * (1.0f - yw);
    float wd = xw * yw;
    int o00 = y0 * W_ + x0, o10 = y1 * W_ + x0;
    int o01 = y0 * W_ + x1, o11 = y1 * W_ + x1;
    const float* ibase = img + (size_t)b * C_ * HW_;
    float* obase = out + (size_t)b * C_ * HW_ + h * W_ + w;
    #pragma unroll
    for (int c = 0; c < C_; c++) {
        const float* p = ibase + c * HW_;
        float Ia = __ldg(p + o00), Ib = __ldg(p + o10);
        float Ic = __ldg(p + o01), Id = __ldg(p + o11);
        obase[c * HW_] = wa * Ia + wb * Ib + wc * Ic + wd * Id;
    }
}

typedef CUresult (*PFN_encode)(CUtensorMap*, CUtensorMapDataType, cuuint32_t,
                               void*, const cuuint64_t*, const cuuint64_t*,
                               const cuuint32_t*, const cuuint32_t*,
                               CUtensorMapInterleave, CUtensorMapSwizzle,
                               CUtensorMapL2promotion, CUtensorMapFloatOOBfill);

extern "C" void kernel_launch(void* const* d_in, const int* in_sizes, int n_in,
                              void* d_out, int out_size)
{
    const float* img = (const float*)d_in[0];
    const float* flo = (const float*)d_in[1];
    float* out = (float*)d_out;

    void* fn = nullptr;
    cudaDriverEntryPointQueryResult qres = cudaDriverEntryPointSymbolNotFound;
    cudaError_t e = cudaGetDriverEntryPoint("cuTensorMapEncodeTiled", &fn,
                                            cudaEnableDefault, &qres);

    bool tma_ok = (e == cudaSuccess && qres == cudaDriverEntryPointSuccess && fn);
    CUtensorMap tmap;
    if (tma_ok) {
        // 4D chunked view of img: {32 (x-in-chunk), 512 (y), 16 (x-chunk),
        // 128 (b*c plane)}; SMEM receives [plane][xc][y][32] with SW128.
        cuuint64_t dims[4]    = {32, 512, 16, (cuuint64_t)(B_ * C_)};
        cuuint64_t strides[3] = {(cuuint64_t)W_ * 4,   // y: 2048 B
                                 32 * 4,               // x-chunk: 128 B
                                 (cuuint64_t)HW_ * 4}; // plane: 1 MB
        cuuint32_t box[4]     = {32, TROWS, 16, 2};
        cuuint32_t estr[4]    = {1, 1, 1, 1};
        CUresult r = ((PFN_encode)fn)(&tmap, CU_TENSOR_MAP_DATA_TYPE_FLOAT32, 4,
                                      (void*)img, dims, strides, box, estr,
                                      CU_TENSOR_MAP_INTERLEAVE_NONE,
                                      CU_TENSOR_MAP_SWIZZLE_128B,
                                      CU_TENSOR_MAP_L2_PROMOTION_L2_128B,
                                      CU_TENSOR_MAP_FLOAT_OOB_FILL_NONE);
        if (r != CUDA_SUCCESS) tma_ok = false;
    }

    if (tma_ok) {
        cudaFuncSetAttribute(warp_bilinear_tma_kernel,
                             cudaFuncAttributeMaxDynamicSharedMemorySize,
                             SMEM_BYTES);
        warp_bilinear_tma_kernel<<<B_ * (H_ / TY), THREADS, SMEM_BYTES>>>(
            tmap, img, flo, out);
    } else {
        const int total = B_ * HW_;
        warp_bilinear_direct_kernel<<<(total + 255) / 256, 256>>>(img, flo, out);
    }
}